// round 15
// baseline (speedup 1.0000x reference)
#include <cuda_runtime.h>
#include <cuda_fp16.h>
#include <cstdint>

// Problem: x [4096, 4096] fp32, A/B [4, 512, 512] fp32 -> out [4096, 16384] fp32
#define G_DIM 4
#define K_BLK 8
#define H_DIM 512
#define N_COLS 2048            // G*H: GEMM output columns (n = g*512 + p)
#define BSZ 4096
#define M_MAIN 32768           // BSZ * K_BLK
#define KDIM 512

// GEMM tiling (base-ISA mma.sync path — sm_103 ptxas has no 'a' features)
#define BM 128
#define BN 128
#define BK 32                  // K elems per stage chunk (64 B fp16 rows)
#define KSTEPS (KDIM / BK)     // 16
#define NTHREADS 256
#define NSTAGES 5
#define TILE_B 8192            // 128 rows x 64 B
#define STAGE_B (2 * TILE_B)   // A + B tiles = 16 KB
#define SMEM_REQ (NSTAGES * STAGE_B)   // 80 KB -> 2 CTAs/SM (160 KB)

// ---------------------------------------------------------------------------
// Static device scratch (no runtime allocation allowed)
// ---------------------------------------------------------------------------
__device__ __half g_Xh[(size_t)M_MAIN * KDIM];   // 32 MB, x fp16
__device__ __half g_Wh[(size_t)N_COLS * KDIM];   // (A-B) fp16
__device__ __half g_Bh[(size_t)N_COLS * KDIM];   // B fp16
__device__ __half g_Sh[(size_t)BSZ * KDIM];      // sum_k x3, fp16
__device__ float  g_T [(size_t)BSZ * N_COLS];    // T = S @ B^T (fp32)

// ---------------------------------------------------------------------------
// Base-ISA PTX helpers (cp.async / ldmatrix / mma.sync)
// ---------------------------------------------------------------------------
__device__ __forceinline__ uint32_t smem_u32(const void* p) {
    return (uint32_t)__cvta_generic_to_shared(p);
}

__device__ __forceinline__ void cp16(uint32_t dst, const void* src) {
    asm volatile("cp.async.cg.shared.global [%0], [%1], 16;"
                 :: "r"(dst), "l"(src) : "memory");
}
__device__ __forceinline__ void cp_commit() {
    asm volatile("cp.async.commit_group;" ::: "memory");
}
template <int N>
__device__ __forceinline__ void cp_wait() {
    asm volatile("cp.async.wait_group %0;" :: "n"(N) : "memory");
}

__device__ __forceinline__ void ldsm4(uint32_t* r, uint32_t a) {
    asm volatile("ldmatrix.sync.aligned.m8n8.x4.shared.b16 {%0,%1,%2,%3}, [%4];"
                 : "=r"(r[0]), "=r"(r[1]), "=r"(r[2]), "=r"(r[3]) : "r"(a));
}

__device__ __forceinline__ void mma_f16(float* c, const uint32_t* a,
                                        uint32_t b0, uint32_t b1) {
    asm volatile(
        "mma.sync.aligned.m16n8k16.row.col.f32.f16.f16.f32 "
        "{%0,%1,%2,%3}, {%4,%5,%6,%7}, {%8,%9}, {%0,%1,%2,%3};"
        : "+f"(c[0]), "+f"(c[1]), "+f"(c[2]), "+f"(c[3])
        : "r"(a[0]), "r"(a[1]), "r"(a[2]), "r"(a[3]), "r"(b0), "r"(b1));
}

// Swizzled smem offset for a 16B chunk: rows of 64 B, chunk c in 0..3.
__device__ __forceinline__ uint32_t sw_off(int row, int c) {
    return (uint32_t)(row * 64 + ((c ^ ((row >> 1) & 3)) << 4));
}

// ---------------------------------------------------------------------------
// Prep kernels
// ---------------------------------------------------------------------------
// W = A - B -> fp16; B -> fp16
__global__ void prep_w_kernel(const float* __restrict__ A, const float* __restrict__ B) {
    int id = blockIdx.x * blockDim.x + threadIdx.x;   // 1048576
    float a = A[id], b = B[id];
    g_Wh[id] = __float2half_rn(a - b);
    g_Bh[id] = __float2half_rn(b);
}

// Fused: x -> fp16 AND S[b,h] = sum_k x[b, k*512+h] (fp32 acc) -> fp16.
__global__ void prep_x_s_kernel(const float* __restrict__ x) {
    const int b = blockIdx.x;            // 0..4095
    const int h = threadIdx.x;           // 0..511
    const float* xr = x + (size_t)b * (K_BLK * H_DIM);
    __half* xo = g_Xh + (size_t)b * (K_BLK * H_DIM);
    float s = 0.f;
#pragma unroll
    for (int k = 0; k < K_BLK; ++k) {
        float v = xr[k * H_DIM + h];
        s += v;
        xo[k * H_DIM + h] = __float2half_rn(v);
    }
    g_Sh[(size_t)b * H_DIM + h] = __float2half_rn(s);
}

// ---------------------------------------------------------------------------
// mma.sync GEMM: D[128,128] per CTA = A[M,K] * B[N,K]^T, fp16 in, f32 acc.
// 8 warps (2x4), warp tile 64x32, 5-stage cp.async pipeline, 1 sync/iter.
// MAIN: out[b, g*4096 + kb*512 + p] = D + T[b, n];  else row-major D store.
// ---------------------------------------------------------------------------
template <bool MAIN>
__global__ void __launch_bounds__(NTHREADS, 2)
mma_gemm_kernel(const __half* __restrict__ Ap,
                const __half* __restrict__ Bp,
                const float* __restrict__ Tadd,
                float* __restrict__ outp)
{
    extern __shared__ __align__(128) char smem[];
    const uint32_t sbase = smem_u32(smem);

    const int tid  = threadIdx.x;
    const int lane = tid & 31;
    const int wid  = tid >> 5;
    const int wm   = wid >> 2;          // 0..1  -> 64-row slab
    const int wn   = wid & 3;           // 0..3  -> 32-col slab

    // ---- staging geometry: each thread copies 2 chunks (16 B) per tile ----
    const int r0 = tid >> 2;            // 0..63
    const int r1 = r0 + 64;
    const int c0 = tid & 3;
    const uint32_t d0 = sw_off(r0, c0);
    const uint32_t d1 = sw_off(r1, c0);
    const size_t oA0 = (size_t)(blockIdx.y * BM + r0) * KDIM + c0 * 8;
    const size_t oA1 = (size_t)(blockIdx.y * BM + r1) * KDIM + c0 * 8;
    const size_t oB0 = (size_t)(blockIdx.x * BN + r0) * KDIM + c0 * 8;
    const size_t oB1 = (size_t)(blockIdx.x * BN + r1) * KDIM + c0 * 8;

    // ---- ldmatrix geometry ----
    const int lr = lane & 15;           // row within 16-row fragment
    const int lc = lane >> 4;           // which 16B k-chunk of the k16
    uint32_t aoff[4], asw[4];
#pragma unroll
    for (int mf = 0; mf < 4; ++mf) {
        const int row = wm * 64 + mf * 16 + lr;
        aoff[mf] = (uint32_t)(row * 64);
        asw[mf]  = (uint32_t)(((row >> 1) & 3) << 4);
    }
    uint32_t boff[2], bsw[2];
#pragma unroll
    for (int nb = 0; nb < 2; ++nb) {
        const int row = wn * 32 + nb * 16 + lr;
        boff[nb] = (uint32_t)(TILE_B + row * 64);
        bsw[nb]  = (uint32_t)(((row >> 1) & 3) << 4);
    }

    float acc[4][4][4];
#pragma unroll
    for (int i = 0; i < 4; ++i)
#pragma unroll
        for (int j = 0; j < 4; ++j)
#pragma unroll
            for (int e = 0; e < 4; ++e) acc[i][j][e] = 0.f;

    // ---- stage loader: A (8 KB) | B (8 KB) ----
    auto load_stage = [&](int buf, int kc) {
        const uint32_t sb = sbase + (uint32_t)(buf * STAGE_B);
        const size_t ke = (size_t)kc * BK;
        cp16(sb + d0,          Ap + oA0 + ke);
        cp16(sb + d1,          Ap + oA1 + ke);
        cp16(sb + TILE_B + d0, Bp + oB0 + ke);
        cp16(sb + TILE_B + d1, Bp + oB1 + ke);
    };

    // ---- prologue: fill stages 0..NSTAGES-2 ----
#pragma unroll
    for (int s = 0; s < NSTAGES - 1; ++s) { load_stage(s, s); cp_commit(); }

    // ---- main loop: one syncthreads per iteration ----
    int cbuf = 0;                       // compute buffer = kc % NSTAGES
    int lbuf = NSTAGES - 1;             // load buffer = (kc + NSTAGES-1) % NSTAGES
#pragma unroll 1
    for (int kc = 0; kc < KSTEPS; ++kc) {
        cp_wait<NSTAGES - 2>();        // stage kc resident
        __syncthreads();
        if (kc + NSTAGES - 1 < KSTEPS) load_stage(lbuf, kc + NSTAGES - 1);
        cp_commit();

        const uint32_t sb = sbase + (uint32_t)(cbuf * STAGE_B);
#pragma unroll
        for (int h = 0; h < 2; ++h) {  // two k16 steps per BK=32
            const uint32_t csel = (uint32_t)((2 * h + lc) << 4);
            uint32_t af[4][4], bf[2][4];
#pragma unroll
            for (int mf = 0; mf < 4; ++mf)
                ldsm4(af[mf], sb + aoff[mf] + (csel ^ asw[mf]));
#pragma unroll
            for (int nb = 0; nb < 2; ++nb)
                ldsm4(bf[nb], sb + boff[nb] + (csel ^ bsw[nb]));
#pragma unroll
            for (int mf = 0; mf < 4; ++mf) {
#pragma unroll
                for (int n8 = 0; n8 < 4; ++n8) {
                    const uint32_t b0 = bf[n8 >> 1][n8 & 1];
                    const uint32_t b1 = bf[n8 >> 1][(n8 & 1) + 2];
                    mma_f16(acc[mf][n8], af[mf], b0, b1);
                }
            }
        }
        if (++cbuf == NSTAGES) cbuf = 0;
        if (++lbuf == NSTAGES) lbuf = 0;
    }

    // ---- epilogue: direct sector-aligned float2 stores ----
    const int m0base = blockIdx.y * BM + wm * 64;
    const int n0base = blockIdx.x * BN + wn * 32;
#pragma unroll
    for (int mf = 0; mf < 4; ++mf) {
#pragma unroll
        for (int n8 = 0; n8 < 4; ++n8) {
            const int n = n0base + n8 * 8 + 2 * (lane & 3);
#pragma unroll
            for (int hf = 0; hf < 2; ++hf) {
                const int m = m0base + mf * 16 + (lane >> 2) + hf * 8;
                float2 v = make_float2(acc[mf][n8][2 * hf], acc[mf][n8][2 * hf + 1]);
                if (MAIN) {
                    const int b  = m >> 3;
                    const int kb = m & 7;
                    const float2 t = *reinterpret_cast<const float2*>(
                        Tadd + (size_t)b * N_COLS + n);
                    v.x += t.x; v.y += t.y;
                    const size_t o = (size_t)b * (G_DIM * K_BLK * H_DIM)
                                   + (size_t)(n >> 9) * (K_BLK * H_DIM)
                                   + (size_t)kb * H_DIM + (n & (H_DIM - 1));
                    *reinterpret_cast<float2*>(outp + o) = v;
                } else {
                    *reinterpret_cast<float2*>(outp + (size_t)m * N_COLS + n) = v;
                }
            }
        }
    }
}

// ---------------------------------------------------------------------------
// Launch
// ---------------------------------------------------------------------------
extern "C" void kernel_launch(void* const* d_in, const int* in_sizes, int n_in,
                              void* d_out, int out_size) {
    const float* x = (const float*)d_in[0];
    const float* A = (const float*)d_in[1];
    const float* B = (const float*)d_in[2];
    float* out = (float*)d_out;

    __half *Xh, *Wh, *Bh, *Sh;
    float* T;
    cudaGetSymbolAddress((void**)&Xh, g_Xh);
    cudaGetSymbolAddress((void**)&Wh, g_Wh);
    cudaGetSymbolAddress((void**)&Bh, g_Bh);
    cudaGetSymbolAddress((void**)&Sh, g_Sh);
    cudaGetSymbolAddress((void**)&T,  g_T);

    cudaFuncSetAttribute(mma_gemm_kernel<false>,
                         cudaFuncAttributeMaxDynamicSharedMemorySize, SMEM_REQ);
    cudaFuncSetAttribute(mma_gemm_kernel<true>,
                         cudaFuncAttributeMaxDynamicSharedMemorySize, SMEM_REQ);

    // 1) W = A-B, B -> fp16
    prep_w_kernel<<<(G_DIM * H_DIM * H_DIM) / 256, 256>>>(A, B);
    // 2) x -> fp16 and S = sum_k x3 -> fp16 (single pass over x)
    prep_x_s_kernel<<<BSZ, H_DIM>>>(x);
    // 3) T = S @ B^T            [4096 x 2048]
    mma_gemm_kernel<false><<<dim3(N_COLS / BN, BSZ / BM), NTHREADS, SMEM_REQ>>>(
        Sh, Bh, nullptr, T);
    // 4) out = remap(X @ W^T + T)  [32768 x 2048]
    mma_gemm_kernel<true><<<dim3(N_COLS / BN, M_MAIN / BM), NTHREADS, SMEM_REQ>>>(
        Xh, Wh, T, out);
}